// round 14
// baseline (speedup 1.0000x reference)
#include <cuda_runtime.h>
#include <math.h>

#define BS_    64
#define KK_    4
#define PTS_   5
#define RES_   28
#define STEPS_ 500
#define NT_    512
#define KSTEPS_ 63          // ceil(504/8)
#define KPAD_  504
#define PIX_ (RES_*RES_)    // 784
#define PSTR_ 34            // padded row stride of C partial
#define PWARP_ (32*PSTR_)   // 1088 floats per buffer

// staging: per-CTA pair-sum of 2 tanh-normed strokes
__device__ float g_pair[2 * BS_ * PIX_];
// per-batch pair counters for fused compose (zero-init; reset each run)
__device__ unsigned int g_cnt[BS_];

__device__ __forceinline__ void mma_tf32(float* d,
                                         unsigned a0, unsigned a1, unsigned a2, unsigned a3,
                                         unsigned b0, unsigned b1) {
    asm volatile(
        "mma.sync.aligned.m16n8k8.row.col.f32.tf32.tf32.f32 "
        "{%0,%1,%2,%3}, {%4,%5,%6,%7}, {%8,%9}, {%0,%1,%2,%3};"
        : "+f"(d[0]), "+f"(d[1]), "+f"(d[2]), "+f"(d[3])
        : "r"(a0), "r"(a1), "r"(a2), "r"(a3), "r"(b0), "r"(b1));
}
__device__ __forceinline__ float ex2f(float x) {
    float r; asm("ex2.approx.ftz.f32 %0, %1;" : "=f"(r) : "f"(x)); return r;
}
__device__ __forceinline__ float rcpf(float x) {
    float r; asm("rcp.approx.ftz.f32 %0, %1;" : "=f"(r) : "f"(x)); return r;
}
// tanh(x) for x >= 0: 1 - 2/(exp(2x)+1)
__device__ __forceinline__ float fast_tanh(float x) {
    const float e = ex2f(x * 2.88539008177793f);
    return 1.0f - 2.0f * rcpf(e + 1.0f);
}
// exp2 of -(d*d)
__device__ __forceinline__ unsigned gauss(float d) {
    return __float_as_uint(ex2f(d * -d));
}

__global__ __launch_bounds__(NT_)
void guide_mma_kernel(const float* __restrict__ z_pres,
                      const float* __restrict__ z_what,
                      const float* __restrict__ z_where,
                      const float* __restrict__ sigma_p,
                      const float* __restrict__ slope_strk_p,
                      const float* __restrict__ slope_p,
                      float* __restrict__ out)
{
    __shared__ float2 curve[2 * KPAD_];      // sqrt-scaled (cx,cy), per local stroke
    __shared__ float  part[8 * PWARP_];      // 4 buffers x 2 strokes (32x34 each)
    __shared__ float  red[32];               // per-warp {max0, max1}
    __shared__ unsigned int slast;

    const int bid    = blockIdx.x;           // 0..127
    const int b      = bid >> 1;
    const int pr     = bid & 1;              // k-pair: strokes {2pr, 2pr+1}
    const int bkbase = b * KK_ + pr * 2;
    const int tid  = threadIdx.x;
    const int wid  = tid >> 5;
    const int lane = tid & 31;
    const int gr   = lane >> 2;              // groupID 0..7
    const int tc   = lane & 3;               // thread-in-group 0..3

    // ---- hoist ALL scalar loads so latency overlaps curve precompute ----
    const float sigma = *sigma_p;
    const float sl    = *slope_strk_p;
    const float sl2   = *slope_p;
    const float zp0   = z_pres[bkbase];
    const float zp1   = z_pres[bkbase + 1];

    const float inv2  = (1.0f / (2.0f * sigma * sigma)) * 1.44269504088896f;
    const float sq    = sqrtf(inv2);         // exp = ex2(-(d*sq)^2)
    const float itsl  = rcpf(fast_tanh(sl));
    const float it2   = rcpf(fast_tanh(sl2));

    // ---- load transform params for both local strokes ----
    float px[2][5], py[2][5];
#pragma unroll
    for (int sk = 0; sk < 2; sk++) {
        const int bk = bkbase + sk;
        const float s   = z_where[bk * 3 + 0];
        const float s0  = z_where[bk * 3 + 1];
        const float s1  = z_where[bk * 3 + 2];
        const float* w = z_what + bk * PTS_ * 2;
#pragma unroll
        for (int i = 0; i < 5; i++) {
            px[sk][i] = w[2*i]   * s + s0;
            py[sk][i] = w[2*i+1] * s + s1;
        }
    }

    // ---- precompute sqrt-scaled curves for both strokes ----
#pragma unroll
    for (int c = 0; c < 2; c++) {
        const int e = tid + c * NT_;
        if (e < 2 * KPAD_) {
            const int sk = (e >= KPAD_) ? 1 : 0;
            const int k  = e - sk * KPAD_;
            float cx = 1e9f, cy = 1e9f;
            if (k < STEPS_) {
                const float u  = (float)k * (1.0f / (float)(STEPS_ - 1));
                const float v  = 1.0f - u;
                const float u2 = u * u, v2 = v * v;
                const float b0 = v2 * v2;
                const float b1 = 4.0f * u * (v * v2);
                const float b2 = 6.0f * u2 * v2;
                const float b3 = 4.0f * (u2 * u) * v;
                const float b4 = u2 * u2;
                cx = b0*px[sk][0] + b1*px[sk][1] + b2*px[sk][2] + b3*px[sk][3] + b4*px[sk][4];
                cy = b0*py[sk][0] + b1*py[sk][1] + b2*py[sk][2] + b3*py[sk][3] + b4*py[sk][4];
            }
            curve[e] = make_float2(cx * sq, cy * sq);
        }
    }
    __syncthreads();

    // per-lane sqrt-scaled grid values for rows/cols {gr, gr+8, gr+16, gr+24}
    float gvs[4];
    gvs[0] = (float)gr        * (1.0f / 27.0f) * sq;
    gvs[1] = (float)(gr + 8)  * (1.0f / 27.0f) * sq;
    gvs[2] = (float)(gr + 16) * (1.0f / 27.0f) * sq;
    gvs[3] = ((gr < 4) ? (float)(gr + 24) * (1.0f / 27.0f) : 1e6f) * sq;

    float D[2][4][4];
#pragma unroll
    for (int mt = 0; mt < 2; mt++)
#pragma unroll
        for (int nt = 0; nt < 4; nt++)
#pragma unroll
            for (int r = 0; r < 4; r++) D[mt][nt][r] = 0.0f;

    // ---- mainloop: warp wid -> stroke (wid&1), ksteps [(wid>>1)*8, +8) ----
    const int sk  = wid & 1;
    const int grp = wid >> 1;                // 0..7
    const int ks0 = grp * 8;
    const int ks1 = (ks0 + 8 < KSTEPS_) ? ks0 + 8 : KSTEPS_;
    const float2* cp = curve + sk * KPAD_ + ks0 * 8 + tc;
#pragma unroll 2
    for (int ks = ks0; ks < ks1; ks++) {
        const float2 cA = cp[0];
        const float2 cB = cp[4];
        cp += 8;

        // B operands (ex, shared by both m-tiles) + mt=0's A operands first
        unsigned ex[4][2];
#pragma unroll
        for (int r = 0; r < 4; r++) {
            ex[r][0] = gauss(gvs[r] - cA.x);
            ex[r][1] = gauss(gvs[r] - cB.x);
        }
        {   // mt = 0: rows 0..15 -> issue its 4 MMAs as soon as ready
            const unsigned a0 = gauss(gvs[0] - cA.y);
            const unsigned a1 = gauss(gvs[1] - cA.y);
            const unsigned a2 = gauss(gvs[0] - cB.y);
            const unsigned a3 = gauss(gvs[1] - cB.y);
#pragma unroll
            for (int nt = 0; nt < 4; nt++)
                mma_tf32(D[0][nt], a0, a1, a2, a3, ex[nt][0], ex[nt][1]);
        }
        {   // mt = 1: rows 16..31
            const unsigned a0 = gauss(gvs[2] - cA.y);
            const unsigned a1 = gauss(gvs[3] - cA.y);
            const unsigned a2 = gauss(gvs[2] - cB.y);
            const unsigned a3 = gauss(gvs[3] - cB.y);
#pragma unroll
            for (int nt = 0; nt < 4; nt++)
                mma_tf32(D[1][nt], a0, a1, a2, a3, ex[nt][0], ex[nt][1]);
        }
    }

    // ---- staged merge: grp 4-7 store, grp 0-3 add (per stroke, 4 buffers) ----
    {
        float* wp = part + (sk * 4 + (grp & 3)) * PWARP_;
        if (grp >= 4) {
#pragma unroll
            for (int mt = 0; mt < 2; mt++)
#pragma unroll
                for (int nt = 0; nt < 4; nt++) {
                    const int row = mt * 16 + gr;
                    const int col = nt * 8 + 2 * tc;
                    float* b0 = wp + row * PSTR_ + col;
                    b0[0] = D[mt][nt][0];
                    b0[1] = D[mt][nt][1];
                    b0[8 * PSTR_]     = D[mt][nt][2];
                    b0[8 * PSTR_ + 1] = D[mt][nt][3];
                }
        }
        __syncthreads();
        if (grp < 4) {
#pragma unroll
            for (int mt = 0; mt < 2; mt++)
#pragma unroll
                for (int nt = 0; nt < 4; nt++) {
                    const int row = mt * 16 + gr;
                    const int col = nt * 8 + 2 * tc;
                    float* b0 = wp + row * PSTR_ + col;
                    b0[0] += D[mt][nt][0];
                    b0[1] += D[mt][nt][1];
                    b0[8 * PSTR_]     += D[mt][nt][2];
                    b0[8 * PSTR_ + 1] += D[mt][nt][3];
                }
        }
    }
    __syncthreads();

    // ---- epilogue: both strokes — sum buffers, zp scale, block max ----
    float myv[2][2];
    float lmax0 = 0.0f, lmax1 = 0.0f;
#pragma unroll
    for (int r = 0; r < 2; r++) {
        const int p = r * NT_ + tid;
        float v0 = 0.0f, v1 = 0.0f;
        if (p < PIX_) {
            const int y = p / RES_;
            const int x = p - y * RES_;
            const int o = y * PSTR_ + x;
            v0 = (part[o] + part[PWARP_ + o] + part[2*PWARP_ + o] + part[3*PWARP_ + o]) * zp0;
            v1 = (part[4*PWARP_ + o] + part[5*PWARP_ + o] + part[6*PWARP_ + o] + part[7*PWARP_ + o]) * zp1;
        }
        myv[0][r] = v0;  myv[1][r] = v1;
        lmax0 = fmaxf(lmax0, v0);
        lmax1 = fmaxf(lmax1, v1);
    }
#pragma unroll
    for (int o = 16; o > 0; o >>= 1) {
        lmax0 = fmaxf(lmax0, __shfl_xor_sync(0xffffffffu, lmax0, o));
        lmax1 = fmaxf(lmax1, __shfl_xor_sync(0xffffffffu, lmax1, o));
    }
    if (lane == 0) { red[wid] = lmax0; red[16 + wid] = lmax1; }
    __syncthreads();
    float bmax0 = red[0], bmax1 = red[16];
#pragma unroll
    for (int w = 1; w < 16; w++) {
        bmax0 = fmaxf(bmax0, red[w]);
        bmax1 = fmaxf(bmax1, red[16 + w]);
    }

    const float sc0 = rcpf(bmax0 + 1e-6f) * sl;
    const float sc1 = rcpf(bmax1 + 1e-6f) * sl;

    // pair-sum of the two tanh-normed strokes; keep in regs AND stage to global
    float psum[2];
    float* gp = g_pair + bid * PIX_;
#pragma unroll
    for (int r = 0; r < 2; r++) {
        const int p = r * NT_ + tid;
        float t = 0.0f;
        if (p < PIX_) {
            t = (fast_tanh(myv[0][r] * sc0) + fast_tanh(myv[1][r] * sc1)) * itsl;
            gp[p] = t;
        }
        psum[r] = t;
    }

    // ---- pair sync (release/acquire): last CTA of batch composes ----
    if (tid == 0) {
        unsigned int old;
        asm volatile("atom.acq_rel.gpu.global.add.u32 %0, [%1], 1;"
                     : "=r"(old) : "l"(&g_cnt[b]) : "memory");
        slast = (old == 1u) ? 1u : 0u;
    }
    __syncthreads();
    if (slast) {
        asm volatile("fence.acq_rel.gpu;" ::: "memory");  // order partner's writes
        const float* gq = g_pair + (bid ^ 1) * PIX_;
#pragma unroll
        for (int r = 0; r < 2; r++) {
            const int p = r * NT_ + tid;
            if (p < PIX_) {
                const float ssum = psum[r] + gq[p];
                out[b * PIX_ + p] = fast_tanh(ssum * sl2) * it2;
            }
        }
        if (tid == 0) g_cnt[b] = 0u;   // reset for next (graph-replayed) call
    }
}

extern "C" void kernel_launch(void* const* d_in, const int* in_sizes, int n_in,
                              void* d_out, int out_size)
{
    const float* z_pres     = (const float*)d_in[0];
    const float* z_what     = (const float*)d_in[1];
    const float* z_where    = (const float*)d_in[2];
    const float* sigma      = (const float*)d_in[3];
    const float* slope_strk = (const float*)d_in[4];
    const float* slope      = (const float*)d_in[5];
    float* out = (float*)d_out;

    guide_mma_kernel<<<2 * BS_, NT_>>>(z_pres, z_what, z_where,
                                       sigma, slope_strk, slope, out);
}

// round 15
// speedup vs baseline: 1.0584x; 1.0584x over previous
#include <cuda_runtime.h>
#include <math.h>

#define BS_    64
#define KK_    4
#define PTS_   5
#define RES_   28
#define STEPS_ 500
#define NT_    512
#define KPAD_  512          // padded k extent (64 ksteps of 8)
#define PIX_ (RES_*RES_)    // 784
#define PSTR_ 34            // padded row stride of C partial
#define PWARP_ (32*PSTR_)   // 1088 floats per buffer

// staging: per-CTA pair-sum of 2 tanh-normed strokes
__device__ float g_pair[2 * BS_ * PIX_];
// per-batch pair counters for fused compose (zero-init; reset each run)
__device__ unsigned int g_cnt[BS_];

__device__ __forceinline__ void mma_tf32(float* d,
                                         unsigned a0, unsigned a1, unsigned a2, unsigned a3,
                                         unsigned b0, unsigned b1) {
    asm volatile(
        "mma.sync.aligned.m16n8k8.row.col.f32.tf32.tf32.f32 "
        "{%0,%1,%2,%3}, {%4,%5,%6,%7}, {%8,%9}, {%0,%1,%2,%3};"
        : "+f"(d[0]), "+f"(d[1]), "+f"(d[2]), "+f"(d[3])
        : "r"(a0), "r"(a1), "r"(a2), "r"(a3), "r"(b0), "r"(b1));
}
__device__ __forceinline__ float ex2f(float x) {
    float r; asm("ex2.approx.ftz.f32 %0, %1;" : "=f"(r) : "f"(x)); return r;
}
__device__ __forceinline__ float rcpf(float x) {
    float r; asm("rcp.approx.ftz.f32 %0, %1;" : "=f"(r) : "f"(x)); return r;
}
// tanh(x) for x >= 0: 1 - 2/(exp(2x)+1)
__device__ __forceinline__ float fast_tanh(float x) {
    const float e = ex2f(x * 2.88539008177793f);
    return 1.0f - 2.0f * rcpf(e + 1.0f);
}
// exp2 of -(d*d)
__device__ __forceinline__ unsigned gauss(float d) {
    return __float_as_uint(ex2f(d * -d));
}

__global__ __launch_bounds__(NT_)
void guide_mma_kernel(const float* __restrict__ z_pres,
                      const float* __restrict__ z_what,
                      const float* __restrict__ z_where,
                      const float* __restrict__ sigma_p,
                      const float* __restrict__ slope_strk_p,
                      const float* __restrict__ slope_p,
                      float* __restrict__ out)
{
    __shared__ float2 curve[2 * KPAD_];      // sqrt-scaled (cx,cy), per local stroke
    __shared__ float  part[8 * PWARP_];      // 4 buffers x 2 strokes (32x34 each)
    __shared__ float  red[32];               // per-warp {max0, max1}
    __shared__ unsigned int slast;

    const int bid    = blockIdx.x;           // 0..127
    const int b      = bid >> 1;
    const int pr     = bid & 1;              // k-pair: strokes {2pr, 2pr+1}
    const int bkbase = b * KK_ + pr * 2;
    const int tid  = threadIdx.x;
    const int wid  = tid >> 5;
    const int lane = tid & 31;
    const int gr   = lane >> 2;              // groupID 0..7
    const int tc   = lane & 3;               // thread-in-group 0..3

    // ---- hoist ALL scalar loads so latency overlaps curve precompute ----
    const float sigma = *sigma_p;
    const float sl    = *slope_strk_p;
    const float sl2   = *slope_p;
    const float zp0   = z_pres[bkbase];
    const float zp1   = z_pres[bkbase + 1];

    const float inv2  = (1.0f / (2.0f * sigma * sigma)) * 1.44269504088896f;
    const float sq    = sqrtf(inv2);         // exp = ex2(-(d*sq)^2)
    const float itsl  = rcpf(fast_tanh(sl));
    const float it2   = rcpf(fast_tanh(sl2));

    // ---- load transform params for both local strokes ----
    float px[2][5], py[2][5];
#pragma unroll
    for (int sk = 0; sk < 2; sk++) {
        const int bk = bkbase + sk;
        const float s   = z_where[bk * 3 + 0];
        const float s0  = z_where[bk * 3 + 1];
        const float s1  = z_where[bk * 3 + 2];
        const float* w = z_what + bk * PTS_ * 2;
#pragma unroll
        for (int i = 0; i < 5; i++) {
            px[sk][i] = w[2*i]   * s + s0;
            py[sk][i] = w[2*i+1] * s + s1;
        }
    }

    // ---- precompute sqrt-scaled curves for both strokes (1024 / 512 thr) ----
#pragma unroll
    for (int c = 0; c < 2; c++) {
        const int e  = tid + c * NT_;
        const int sk = (e >= KPAD_) ? 1 : 0;
        const int k  = e - sk * KPAD_;
        float cx = 1e9f, cy = 1e9f;
        if (k < STEPS_) {
            const float u  = (float)k * (1.0f / (float)(STEPS_ - 1));
            const float v  = 1.0f - u;
            const float u2 = u * u, v2 = v * v;
            const float b0 = v2 * v2;
            const float b1 = 4.0f * u * (v * v2);
            const float b2 = 6.0f * u2 * v2;
            const float b3 = 4.0f * (u2 * u) * v;
            const float b4 = u2 * u2;
            cx = b0*px[sk][0] + b1*px[sk][1] + b2*px[sk][2] + b3*px[sk][3] + b4*px[sk][4];
            cy = b0*py[sk][0] + b1*py[sk][1] + b2*py[sk][2] + b3*py[sk][3] + b4*py[sk][4];
        }
        curve[e] = make_float2(cx * sq, cy * sq);
    }
    __syncthreads();

    // per-lane sqrt-scaled grid values for rows/cols {gr, gr+8, gr+16, gr+24}
    float gvs[4];
    gvs[0] = (float)gr        * (1.0f / 27.0f) * sq;
    gvs[1] = (float)(gr + 8)  * (1.0f / 27.0f) * sq;
    gvs[2] = (float)(gr + 16) * (1.0f / 27.0f) * sq;
    gvs[3] = ((gr < 4) ? (float)(gr + 24) * (1.0f / 27.0f) : 1e6f) * sq;

    // ---- preload this lane's 16 curve points into registers ----
    const int sk  = wid & 1;
    const int grp = wid >> 1;                // 0..7, owns ksteps [grp*8, grp*8+8)
    const float2* cp = curve + sk * KPAD_ + grp * 64 + tc;
    float2 cv[16];
#pragma unroll
    for (int j = 0; j < 8; j++) {
        cv[2*j]   = cp[j * 8];       // kA   of kstep j
        cv[2*j+1] = cp[j * 8 + 4];   // kA+4 of kstep j
    }

    float D[2][4][4];
#pragma unroll
    for (int mt = 0; mt < 2; mt++)
#pragma unroll
        for (int nt = 0; nt < 4; nt++)
#pragma unroll
            for (int r = 0; r < 4; r++) D[mt][nt][r] = 0.0f;

    // ---- fully-unrolled register-resident mainloop: 8 ksteps ----
#pragma unroll
    for (int j = 0; j < 8; j++) {
        const float2 cA = cv[2*j];
        const float2 cB = cv[2*j+1];

        unsigned ey[4][2], ex[4][2];
#pragma unroll
        for (int r = 0; r < 4; r++) {
            ey[r][0] = gauss(gvs[r] - cA.y);
            ey[r][1] = gauss(gvs[r] - cB.y);
            ex[r][0] = gauss(gvs[r] - cA.x);
            ex[r][1] = gauss(gvs[r] - cB.x);
        }

#pragma unroll
        for (int mt = 0; mt < 2; mt++) {
            const unsigned a0 = ey[2*mt][0], a1 = ey[2*mt+1][0];
            const unsigned a2 = ey[2*mt][1], a3 = ey[2*mt+1][1];
#pragma unroll
            for (int nt = 0; nt < 4; nt++)
                mma_tf32(D[mt][nt], a0, a1, a2, a3, ex[nt][0], ex[nt][1]);
        }
    }

    // ---- staged merge: grp 4-7 store, grp 0-3 add (per stroke, 4 buffers) ----
    {
        float* wp = part + (sk * 4 + (grp & 3)) * PWARP_;
        if (grp >= 4) {
#pragma unroll
            for (int mt = 0; mt < 2; mt++)
#pragma unroll
                for (int nt = 0; nt < 4; nt++) {
                    const int row = mt * 16 + gr;
                    const int col = nt * 8 + 2 * tc;
                    float* b0 = wp + row * PSTR_ + col;
                    b0[0] = D[mt][nt][0];
                    b0[1] = D[mt][nt][1];
                    b0[8 * PSTR_]     = D[mt][nt][2];
                    b0[8 * PSTR_ + 1] = D[mt][nt][3];
                }
        }
        __syncthreads();
        if (grp < 4) {
#pragma unroll
            for (int mt = 0; mt < 2; mt++)
#pragma unroll
                for (int nt = 0; nt < 4; nt++) {
                    const int row = mt * 16 + gr;
                    const int col = nt * 8 + 2 * tc;
                    float* b0 = wp + row * PSTR_ + col;
                    b0[0] += D[mt][nt][0];
                    b0[1] += D[mt][nt][1];
                    b0[8 * PSTR_]     += D[mt][nt][2];
                    b0[8 * PSTR_ + 1] += D[mt][nt][3];
                }
        }
    }
    __syncthreads();

    // ---- epilogue: both strokes — sum buffers, zp scale, block max ----
    float myv[2][2];
    float lmax0 = 0.0f, lmax1 = 0.0f;
#pragma unroll
    for (int r = 0; r < 2; r++) {
        const int p = r * NT_ + tid;
        float v0 = 0.0f, v1 = 0.0f;
        if (p < PIX_) {
            const int y = p / RES_;
            const int x = p - y * RES_;
            const int o = y * PSTR_ + x;
            v0 = (part[o] + part[PWARP_ + o] + part[2*PWARP_ + o] + part[3*PWARP_ + o]) * zp0;
            v1 = (part[4*PWARP_ + o] + part[5*PWARP_ + o] + part[6*PWARP_ + o] + part[7*PWARP_ + o]) * zp1;
        }
        myv[0][r] = v0;  myv[1][r] = v1;
        lmax0 = fmaxf(lmax0, v0);
        lmax1 = fmaxf(lmax1, v1);
    }
#pragma unroll
    for (int o = 16; o > 0; o >>= 1) {
        lmax0 = fmaxf(lmax0, __shfl_xor_sync(0xffffffffu, lmax0, o));
        lmax1 = fmaxf(lmax1, __shfl_xor_sync(0xffffffffu, lmax1, o));
    }
    if (lane == 0) { red[wid] = lmax0; red[16 + wid] = lmax1; }
    __syncthreads();
    float bmax0 = red[0], bmax1 = red[16];
#pragma unroll
    for (int w = 1; w < 16; w++) {
        bmax0 = fmaxf(bmax0, red[w]);
        bmax1 = fmaxf(bmax1, red[16 + w]);
    }

    const float sc0 = rcpf(bmax0 + 1e-6f) * sl;
    const float sc1 = rcpf(bmax1 + 1e-6f) * sl;

    // pair-sum of the two tanh-normed strokes; keep in regs AND stage to global
    float psum[2];
    float* gp = g_pair + bid * PIX_;
#pragma unroll
    for (int r = 0; r < 2; r++) {
        const int p = r * NT_ + tid;
        float t = 0.0f;
        if (p < PIX_) {
            t = (fast_tanh(myv[0][r] * sc0) + fast_tanh(myv[1][r] * sc1)) * itsl;
            gp[p] = t;
        }
        psum[r] = t;
    }

    // ---- pair sync (release/acquire): last CTA of batch composes ----
    if (tid == 0) {
        unsigned int old;
        asm volatile("atom.acq_rel.gpu.global.add.u32 %0, [%1], 1;"
                     : "=r"(old) : "l"(&g_cnt[b]) : "memory");
        slast = (old == 1u) ? 1u : 0u;
    }
    __syncthreads();
    if (slast) {
        asm volatile("fence.acq_rel.gpu;" ::: "memory");  // order partner's writes
        const float* gq = g_pair + (bid ^ 1) * PIX_;
#pragma unroll
        for (int r = 0; r < 2; r++) {
            const int p = r * NT_ + tid;
            if (p < PIX_) {
                const float ssum = psum[r] + gq[p];
                out[b * PIX_ + p] = fast_tanh(ssum * sl2) * it2;
            }
        }
        if (tid == 0) g_cnt[b] = 0u;   // reset for next (graph-replayed) call
    }
}

extern "C" void kernel_launch(void* const* d_in, const int* in_sizes, int n_in,
                              void* d_out, int out_size)
{
    const float* z_pres     = (const float*)d_in[0];
    const float* z_what     = (const float*)d_in[1];
    const float* z_where    = (const float*)d_in[2];
    const float* sigma      = (const float*)d_in[3];
    const float* slope_strk = (const float*)d_in[4];
    const float* slope      = (const float*)d_in[5];
    float* out = (float*)d_out;

    guide_mma_kernel<<<2 * BS_, NT_>>>(z_pres, z_what, z_where,
                                       sigma, slope_strk, slope, out);
}

// round 16
// speedup vs baseline: 1.1910x; 1.1254x over previous
#include <cuda_runtime.h>
#include <math.h>

#define BS_    64
#define KK_    4
#define PTS_   5
#define RES_   28
#define STEPS_ 500
#define NT_    512
#define PIX_ (RES_*RES_)    // 784
#define HPIX_ 392
#define PSTR_ 34            // padded row stride of C partial
#define PWARP_ (32*PSTR_)   // 1088 floats per buffer

// staging: per-CTA pair-sum of 2 tanh-normed strokes
__device__ float g_pair[2 * BS_ * PIX_];
// per-batch pair counters (zero-init; reset by first-arriver each run)
__device__ unsigned int g_cnt[BS_];

__device__ __forceinline__ void mma_tf32(float* d,
                                         unsigned a0, unsigned a1, unsigned a2, unsigned a3,
                                         unsigned b0, unsigned b1) {
    asm volatile(
        "mma.sync.aligned.m16n8k8.row.col.f32.tf32.tf32.f32 "
        "{%0,%1,%2,%3}, {%4,%5,%6,%7}, {%8,%9}, {%0,%1,%2,%3};"
        : "+f"(d[0]), "+f"(d[1]), "+f"(d[2]), "+f"(d[3])
        : "r"(a0), "r"(a1), "r"(a2), "r"(a3), "r"(b0), "r"(b1));
}
__device__ __forceinline__ float ex2f(float x) {
    float r; asm("ex2.approx.ftz.f32 %0, %1;" : "=f"(r) : "f"(x)); return r;
}
__device__ __forceinline__ float rcpf(float x) {
    float r; asm("rcp.approx.ftz.f32 %0, %1;" : "=f"(r) : "f"(x)); return r;
}
// tanh(x) for x >= 0: 1 - 2/(exp(2x)+1)
__device__ __forceinline__ float fast_tanh(float x) {
    const float e = ex2f(x * 2.88539008177793f);
    return 1.0f - 2.0f * rcpf(e + 1.0f);
}
// exp2 of -(d*d)
__device__ __forceinline__ unsigned gauss(float d) {
    return __float_as_uint(ex2f(d * -d));
}

__global__ __launch_bounds__(NT_)
void guide_mma_kernel(const float* __restrict__ z_pres,
                      const float* __restrict__ z_what,
                      const float* __restrict__ z_where,
                      const float* __restrict__ sigma_p,
                      const float* __restrict__ slope_strk_p,
                      const float* __restrict__ slope_p,
                      float* __restrict__ out)
{
    __shared__ float  part[8 * PWARP_];      // 4 buffers x 2 strokes (32x34 each)
    __shared__ float  pairbuf[PIX_];         // this CTA's tanh pair-sum
    __shared__ float  red[32];               // per-warp {max0, max1}

    const int bid    = blockIdx.x;           // 0..127
    const int b      = bid >> 1;
    const int pr     = bid & 1;              // k-pair: strokes {2pr, 2pr+1}
    const int bkbase = b * KK_ + pr * 2;
    const int tid  = threadIdx.x;
    const int wid  = tid >> 5;
    const int lane = tid & 31;
    const int gr   = lane >> 2;              // groupID 0..7
    const int tc   = lane & 3;               // thread-in-group 0..3

    // ---- hoist ALL scalar loads ----
    const float sigma = *sigma_p;
    const float sl    = *slope_strk_p;
    const float sl2   = *slope_p;
    const float zp0   = z_pres[bkbase];
    const float zp1   = z_pres[bkbase + 1];

    const float inv2  = (1.0f / (2.0f * sigma * sigma)) * 1.44269504088896f;
    const float sq    = sqrtf(inv2);         // exp = ex2(-(d*sq)^2)
    const float itsl  = rcpf(fast_tanh(sl));
    const float it2   = rcpf(fast_tanh(sl2));

    // ---- this warp's stroke: control points -> power basis (scaled by sq) ----
    const int sk  = wid & 1;
    const int grp = wid >> 1;                // 0..7, owns ksteps [grp*8, grp*8+8)
    float ax0, ax1, ax2, ax3, ax4, ay0, ay1, ay2, ay3, ay4;
    {
        const int bk = bkbase + sk;
        const float s  = z_where[bk * 3 + 0];
        const float s0 = z_where[bk * 3 + 1];
        const float s1 = z_where[bk * 3 + 2];
        const float* w = z_what + bk * PTS_ * 2;
        const float p0x = w[0]*s + s0, p0y = w[1]*s + s1;
        const float p1x = w[2]*s + s0, p1y = w[3]*s + s1;
        const float p2x = w[4]*s + s0, p2y = w[5]*s + s1;
        const float p3x = w[6]*s + s0, p3y = w[7]*s + s1;
        const float p4x = w[8]*s + s0, p4y = w[9]*s + s1;
        ax0 = p0x * sq;
        ax1 = 4.0f * (p1x - p0x) * sq;
        ax2 = 6.0f * (p2x - 2.0f*p1x + p0x) * sq;
        ax3 = 4.0f * (p3x - 3.0f*p2x + 3.0f*p1x - p0x) * sq;
        ax4 = (p4x - 4.0f*p3x + 6.0f*p2x - 4.0f*p1x + p0x) * sq;
        ay0 = p0y * sq;
        ay1 = 4.0f * (p1y - p0y) * sq;
        ay2 = 6.0f * (p2y - 2.0f*p1y + p0y) * sq;
        ay3 = 4.0f * (p3y - 3.0f*p2y + 3.0f*p1y - p0y) * sq;
        ay4 = (p4y - 4.0f*p3y + 6.0f*p2y - 4.0f*p1y + p0y) * sq;
    }

    // ---- per-lane register curve gen: 16 points (kA, kA+4 for 8 ksteps) ----
    float2 cv[16];
    {
        const int kbase = grp * 64 + tc;
#pragma unroll
        for (int j = 0; j < 8; j++) {
#pragma unroll
            for (int h = 0; h < 2; h++) {
                const int k = kbase + j * 8 + h * 4;
                const float u = (float)k * (1.0f / (float)(STEPS_ - 1));
                float cx = (((ax4*u + ax3)*u + ax2)*u + ax1)*u + ax0;
                float cy = (((ay4*u + ay3)*u + ay2)*u + ay1)*u + ay0;
                if (k >= STEPS_) { cx = 1e9f; cy = 1e9f; }
                cv[2*j + h] = make_float2(cx, cy);
            }
        }
    }

    // per-lane sqrt-scaled grid values for rows/cols {gr, gr+8, gr+16, gr+24}
    float gvs[4];
    gvs[0] = (float)gr        * (1.0f / 27.0f) * sq;
    gvs[1] = (float)(gr + 8)  * (1.0f / 27.0f) * sq;
    gvs[2] = (float)(gr + 16) * (1.0f / 27.0f) * sq;
    gvs[3] = ((gr < 4) ? (float)(gr + 24) * (1.0f / 27.0f) : 1e6f) * sq;

    float D[2][4][4];
#pragma unroll
    for (int mt = 0; mt < 2; mt++)
#pragma unroll
        for (int nt = 0; nt < 4; nt++)
#pragma unroll
            for (int r = 0; r < 4; r++) D[mt][nt][r] = 0.0f;

    // ---- fully-unrolled register-resident mainloop: 8 ksteps ----
#pragma unroll
    for (int j = 0; j < 8; j++) {
        const float2 cA = cv[2*j];
        const float2 cB = cv[2*j+1];

        unsigned ey[4][2], ex[4][2];
#pragma unroll
        for (int r = 0; r < 4; r++) {
            ey[r][0] = gauss(gvs[r] - cA.y);
            ey[r][1] = gauss(gvs[r] - cB.y);
            ex[r][0] = gauss(gvs[r] - cA.x);
            ex[r][1] = gauss(gvs[r] - cB.x);
        }

#pragma unroll
        for (int mt = 0; mt < 2; mt++) {
            const unsigned a0 = ey[2*mt][0], a1 = ey[2*mt+1][0];
            const unsigned a2 = ey[2*mt][1], a3 = ey[2*mt+1][1];
#pragma unroll
            for (int nt = 0; nt < 4; nt++)
                mma_tf32(D[mt][nt], a0, a1, a2, a3, ex[nt][0], ex[nt][1]);
        }
    }

    // ---- staged merge: grp 4-7 store, grp 0-3 add (per stroke, 4 buffers) ----
    {
        float* wp = part + (sk * 4 + (grp & 3)) * PWARP_;
        if (grp >= 4) {
#pragma unroll
            for (int mt = 0; mt < 2; mt++)
#pragma unroll
                for (int nt = 0; nt < 4; nt++) {
                    const int row = mt * 16 + gr;
                    const int col = nt * 8 + 2 * tc;
                    float* b0 = wp + row * PSTR_ + col;
                    b0[0] = D[mt][nt][0];
                    b0[1] = D[mt][nt][1];
                    b0[8 * PSTR_]     = D[mt][nt][2];
                    b0[8 * PSTR_ + 1] = D[mt][nt][3];
                }
        }
        __syncthreads();
        if (grp < 4) {
#pragma unroll
            for (int mt = 0; mt < 2; mt++)
#pragma unroll
                for (int nt = 0; nt < 4; nt++) {
                    const int row = mt * 16 + gr;
                    const int col = nt * 8 + 2 * tc;
                    float* b0 = wp + row * PSTR_ + col;
                    b0[0] += D[mt][nt][0];
                    b0[1] += D[mt][nt][1];
                    b0[8 * PSTR_]     += D[mt][nt][2];
                    b0[8 * PSTR_ + 1] += D[mt][nt][3];
                }
        }
    }
    __syncthreads();

    // ---- epilogue: both strokes — sum buffers, zp scale, block max ----
    float myv[2][2];
    float lmax0 = 0.0f, lmax1 = 0.0f;
#pragma unroll
    for (int r = 0; r < 2; r++) {
        const int p = r * NT_ + tid;
        float v0 = 0.0f, v1 = 0.0f;
        if (p < PIX_) {
            const int y = p / RES_;
            const int x = p - y * RES_;
            const int o = y * PSTR_ + x;
            v0 = (part[o] + part[PWARP_ + o] + part[2*PWARP_ + o] + part[3*PWARP_ + o]) * zp0;
            v1 = (part[4*PWARP_ + o] + part[5*PWARP_ + o] + part[6*PWARP_ + o] + part[7*PWARP_ + o]) * zp1;
        }
        myv[0][r] = v0;  myv[1][r] = v1;
        lmax0 = fmaxf(lmax0, v0);
        lmax1 = fmaxf(lmax1, v1);
    }
#pragma unroll
    for (int o = 16; o > 0; o >>= 1) {
        lmax0 = fmaxf(lmax0, __shfl_xor_sync(0xffffffffu, lmax0, o));
        lmax1 = fmaxf(lmax1, __shfl_xor_sync(0xffffffffu, lmax1, o));
    }
    if (lane == 0) { red[wid] = lmax0; red[16 + wid] = lmax1; }
    __syncthreads();
    float bmax0 = red[0], bmax1 = red[16];
#pragma unroll
    for (int w = 1; w < 16; w++) {
        bmax0 = fmaxf(bmax0, red[w]);
        bmax1 = fmaxf(bmax1, red[16 + w]);
    }

    const float sc0 = rcpf(bmax0 + 1e-6f) * sl;
    const float sc1 = rcpf(bmax1 + 1e-6f) * sl;

    // pair-sum of the two tanh-normed strokes -> smem pairbuf + global stage
    float* gp = g_pair + bid * PIX_;
#pragma unroll
    for (int r = 0; r < 2; r++) {
        const int p = r * NT_ + tid;
        if (p < PIX_) {
            const float t = (fast_tanh(myv[0][r] * sc0) + fast_tanh(myv[1][r] * sc1)) * itsl;
            pairbuf[p] = t;
            gp[p] = t;
        }
    }
    __syncthreads();   // all gp/pairbuf writes done before arrival

    // ---- symmetric pair sync: arrive; first arriver spins then resets ----
    if (tid == 0) {
        unsigned int old;
        asm volatile("atom.acq_rel.gpu.global.add.u32 %0, [%1], 1;"
                     : "=r"(old) : "l"(&g_cnt[b]) : "memory");
        if (old == 0u) {
            unsigned int v;
            do {
                asm volatile("ld.acquire.gpu.global.u32 %0, [%1];"
                             : "=r"(v) : "l"(&g_cnt[b]) : "memory");
            } while (v < 2u);
            asm volatile("st.relaxed.gpu.global.u32 [%0], %1;"
                         :: "l"(&g_cnt[b]), "r"(0u) : "memory");
        }
    }
    __syncthreads();   // partner's data now visible to all threads

    // ---- both CTAs compose their half of the output image ----
    if (tid < HPIX_) {
        const int p = pr * HPIX_ + tid;
        const float* gq = g_pair + (bid ^ 1) * PIX_;
        const float ssum = pairbuf[p] + gq[p];
        out[b * PIX_ + p] = fast_tanh(ssum * sl2) * it2;
    }
}

extern "C" void kernel_launch(void* const* d_in, const int* in_sizes, int n_in,
                              void* d_out, int out_size)
{
    const float* z_pres     = (const float*)d_in[0];
    const float* z_what     = (const float*)d_in[1];
    const float* z_where    = (const float*)d_in[2];
    const float* sigma      = (const float*)d_in[3];
    const float* slope_strk = (const float*)d_in[4];
    const float* slope      = (const float*)d_in[5];
    float* out = (float*)d_out;

    guide_mma_kernel<<<2 * BS_, NT_>>>(z_pres, z_what, z_where,
                                       sigma, slope_strk, slope, out);
}